// round 15
// baseline (speedup 1.0000x reference)
#include <cuda_runtime.h>
#include <cuda_fp16.h>
#include <cstdint>
#include <cstddef>

// Problem constants
constexpr int BB   = 2;
constexpr int SEQ  = 2048;
constexpr int DIMM = 2048;
constexpr int NH   = 32;
constexpr int NKV  = 8;
constexpr int HDIM = 64;
constexpr int MROWS = BB * SEQ;                    // 4096
constexpr int NQKV  = NH * HDIM + 2 * NKV * HDIM;  // 3072

// ---------------------------------------------------------------------------
// Scratch (device globals; allocation-free rule)
// ---------------------------------------------------------------------------
__device__ uint32_t g_xt[MROWS * DIMM / 2];         // packed x           16 MB
__device__ uint32_t g_wqkvt[NQKV * DIMM / 2];       // packed wq|wk|wv    12 MB
__device__ uint32_t g_wot[DIMM * DIMM / 2];         // packed wo           8 MB
__device__ uint32_t g_at[MROWS * DIMM / 2];         // packed attn out    16 MB
__device__ __half g_qs[BB * NH * SEQ * HDIM];       // 16 MB (q roped, /8)
__device__ __half g_ks[BB * NKV * SEQ * HDIM];      // 4 MB  (k roped)
__device__ __half g_vs[BB * NKV * SEQ * HDIM];      // 4 MB

// ---------------------------------------------------------------------------
// Helpers
// ---------------------------------------------------------------------------
__device__ __forceinline__ uint32_t smem_u32(const void* p) {
    uint32_t a;
    asm("{ .reg .u64 t; cvta.to.shared.u64 t, %1; cvt.u32.u64 %0, t; }" : "=r"(a) : "l"(p));
    return a;
}
__device__ __forceinline__ void cp_async16(uint32_t dst, const void* src) {
    asm volatile("cp.async.cg.shared.global [%0], [%1], 16;" :: "r"(dst), "l"(src));
}
__device__ __forceinline__ void cp_commit() { asm volatile("cp.async.commit_group;" ::: "memory"); }

__device__ __forceinline__ void lds128(uint32_t* r, uint32_t addr) {
    asm volatile("ld.shared.v4.b32 {%0,%1,%2,%3}, [%4];"
        : "=r"(r[0]), "=r"(r[1]), "=r"(r[2]), "=r"(r[3]) : "r"(addr));
}
__device__ __forceinline__ void ldm_x4(uint32_t* r, uint32_t addr) {
    asm volatile("ldmatrix.sync.aligned.m8n8.x4.shared.b16 {%0,%1,%2,%3}, [%4];"
        : "=r"(r[0]), "=r"(r[1]), "=r"(r[2]), "=r"(r[3]) : "r"(addr));
}
__device__ __forceinline__ void ldm_x4_t(uint32_t* r, uint32_t addr) {
    asm volatile("ldmatrix.sync.aligned.m8n8.x4.trans.shared.b16 {%0,%1,%2,%3}, [%4];"
        : "=r"(r[0]), "=r"(r[1]), "=r"(r[2]), "=r"(r[3]) : "r"(addr));
}
__device__ __forceinline__ void mma_f16(float* d, const uint32_t* a, uint32_t b0, uint32_t b1) {
    asm volatile("mma.sync.aligned.m16n8k16.row.col.f32.f16.f16.f32 "
        "{%0,%1,%2,%3}, {%4,%5,%6,%7}, {%8,%9}, {%0,%1,%2,%3};"
        : "+f"(d[0]), "+f"(d[1]), "+f"(d[2]), "+f"(d[3])
        : "r"(a[0]), "r"(a[1]), "r"(a[2]), "r"(a[3]), "r"(b0), "r"(b1));
}
__device__ __forceinline__ uint32_t f2h2(float lo, float hi) {
    __half2 h = __floats2half2_rn(lo, hi);
    return *(uint32_t*)&h;
}
__device__ __forceinline__ float ex2f(float x) {
    float r;
    asm("ex2.approx.f32 %0, %1;" : "=f"(r) : "f"(x));
    return r;
}

// ---------------------------------------------------------------------------
// pack_main: x (A-pack, blocks [0,4096)) + merged qkv weights (B-pack,
// blocks [4096,7168)).
// ---------------------------------------------------------------------------
__global__ __launch_bounds__(256) void pack_main(const float* __restrict__ x,
                                                 const float* __restrict__ wq,
                                                 const float* __restrict__ wk,
                                                 const float* __restrict__ wv) {
    const int blk = blockIdx.x;
    if (blk < 4096) {
        int idx = blk * 256 + threadIdx.x;
        int lane = idx & 31;
        int kc16 = (idx >> 5) & 127;
        int mb = idx >> 12;
        int r = lane >> 2;
        int c2 = kc16 * 16 + (lane & 3) * 2;
        const float* s = x + (size_t)mb * 16 * 2048;
        uint4 o;
        o.x = f2h2(s[(size_t)r * 2048 + c2],        s[(size_t)r * 2048 + c2 + 1]);
        o.y = f2h2(s[(size_t)(r + 8) * 2048 + c2],  s[(size_t)(r + 8) * 2048 + c2 + 1]);
        o.z = f2h2(s[(size_t)r * 2048 + c2 + 8],    s[(size_t)r * 2048 + c2 + 9]);
        o.w = f2h2(s[(size_t)(r + 8) * 2048 + c2 + 8], s[(size_t)(r + 8) * 2048 + c2 + 9]);
        ((uint4*)g_xt)[(size_t)mb * 4096 + (idx & 4095)] = o;
    } else {
        int idx = (blk - 4096) * 256 + threadIdx.x;
        int lane = idx & 31;
        int nb = idx >> 11;
        int kc32 = (idx >> 5) & 63;
        int n = nb * 8 + (lane >> 2);
        int k2 = kc32 * 32 + (lane & 3) * 2;
        const float* s;
        if (n < 2048)      s = wq + (size_t)n * 2048 + k2;
        else if (n < 2560) s = wk + (size_t)(n - 2048) * 2048 + k2;
        else               s = wv + (size_t)(n - 2560) * 2048 + k2;
        uint4 o;
        o.x = f2h2(s[0],  s[1]);
        o.y = f2h2(s[8],  s[9]);
        o.z = f2h2(s[16], s[17]);
        o.w = f2h2(s[24], s[25]);
        ((uint4*)g_wqkvt)[idx] = o;
    }
}

// pack_wo: wo B-pack, 2048 blocks (runs on side stream).
__global__ __launch_bounds__(256) void pack_wo(const float* __restrict__ wo) {
    int idx = blockIdx.x * 256 + threadIdx.x;
    int lane = idx & 31;
    int nb = idx >> 11;
    int kc32 = (idx >> 5) & 63;
    int n = nb * 8 + (lane >> 2);
    int k2 = kc32 * 32 + (lane & 3) * 2;
    const float* s = wo + (size_t)n * 2048 + k2;
    uint4 o;
    o.x = f2h2(s[0],  s[1]);
    o.y = f2h2(s[8],  s[9]);
    o.z = f2h2(s[16], s[17]);
    o.w = f2h2(s[24], s[25]);
    ((uint4*)g_wot)[idx] = o;
}

// ---------------------------------------------------------------------------
// GEMM mainloop: CTA 128x128, 256 thr, warps 2x4 (warp tile 64x32),
// K-chunk 32, 4-stage cp.async pipeline, 2 CTAs/SM. ybase = M-block offset.
// ---------------------------------------------------------------------------
constexpr int FSTAGE = 16384;
constexpr int GSMEM  = 4 * FSTAGE;                 // 65536

struct GemmCtx {
    float acc[4][4][4];
    int bm, bn, wid, L;
};

__device__ __forceinline__ void gemm_mainloop(const uint32_t* __restrict__ A,
                                              const uint32_t* __restrict__ B,
                                              GemmCtx& cx, char* dsm, int ybase) {
    const int tid = threadIdx.x;
    const int wid = tid >> 5;
    const int L = tid & 31;
    const uint32_t base = smem_u32(dsm);
    cx.bm = (blockIdx.y + ybase) * 128;
    cx.bn = blockIdx.x * 128;
    cx.wid = wid; cx.L = L;
    const uint32_t* Ab = A + (size_t)(cx.bm >> 4) * 16384;
    const uint32_t* Bb = B + (size_t)(cx.bn >> 3) * 8192;

#pragma unroll
    for (int i = 0; i < 4; i++)
#pragma unroll
        for (int j = 0; j < 4; j++)
#pragma unroll
            for (int q = 0; q < 4; q++) cx.acc[i][j][q] = 0.f;

    auto load_stage = [&](int s, int c) {
        const uint32_t sb = base + s * FSTAGE;
#pragma unroll
        for (int u = 0; u < 2; u++) {
            int e = tid + u * 256;
            int lane = e & 31, kcl = (e >> 5) & 1, mb = e >> 6;
            cp_async16(sb + e * 16,
                       Ab + (((size_t)mb * 128 + c * 2 + kcl) * 32 + lane) * 4);
        }
#pragma unroll
        for (int u = 0; u < 2; u++) {
            int e = tid + u * 256;
            int lane = e & 31, nb = e >> 5;
            cp_async16(sb + 8192 + e * 16,
                       Bb + (((size_t)nb * 64 + c) * 32 + lane) * 4);
        }
    };

    load_stage(0, 0); cp_commit();
    load_stage(1, 1); cp_commit();
    load_stage(2, 2); cp_commit();

    const int wmb = (wid >> 2) * 4;
    const int wnb = (wid & 3) * 4;

    for (int i = 0; i < 64; i++) {
        if (i + 3 < 64) load_stage((i + 3) & 3, i + 3);
        cp_commit();
        asm volatile("cp.async.wait_group 3;" ::: "memory");
        __syncthreads();

        const uint32_t sA = base + (i & 3) * FSTAGE;
        const uint32_t sB = sA + 8192;
        uint32_t b[4][4];
#pragma unroll
        for (int g = 0; g < 4; g++)
            lds128(b[g], sB + (((wnb + g) * 32) + L) * 16);
#pragma unroll
        for (int kcl = 0; kcl < 2; kcl++) {
            uint32_t a[4][4];
#pragma unroll
            for (int am = 0; am < 4; am++)
                lds128(a[am], sA + (((wmb + am) * 2 + kcl) * 32 + L) * 16);
#pragma unroll
            for (int am = 0; am < 4; am++)
#pragma unroll
                for (int g = 0; g < 4; g++)
                    mma_f16(cx.acc[am][g], a[am], b[g][2 * kcl], b[g][2 * kcl + 1]);
        }
        __syncthreads();
    }
}

// ---------------------------------------------------------------------------
// O-projection GEMM (per batch half): fp32 epilogue to d_out.
// ---------------------------------------------------------------------------
__global__ __launch_bounds__(256, 2)
void gemm_f16(const uint32_t* __restrict__ A, const uint32_t* __restrict__ B,
              float* __restrict__ C, int Ntot, int ybase) {
    extern __shared__ __align__(128) char dsm[];
    GemmCtx cx;
    gemm_mainloop(A, B, cx, dsm, ybase);
#pragma unroll
    for (int am = 0; am < 4; am++) {
        int row = cx.bm + (cx.wid >> 2) * 64 + am * 16 + (cx.L >> 2);
#pragma unroll
        for (int g = 0; g < 4; g++) {
            int col = cx.bn + (cx.wid & 3) * 32 + g * 8 + (cx.L & 3) * 2;
            *(float2*)(C + (size_t)row * Ntot + col) = make_float2(cx.acc[am][g][0], cx.acc[am][g][1]);
            *(float2*)(C + (size_t)(row + 8) * Ntot + col) = make_float2(cx.acc[am][g][2], cx.acc[am][g][3]);
        }
    }
}

// ---------------------------------------------------------------------------
// QKV GEMM (per batch half) with fused RoPE + fp16 epilogue.
// ---------------------------------------------------------------------------
__global__ __launch_bounds__(256, 2)
void gemm_qkv(const uint32_t* __restrict__ A, const uint32_t* __restrict__ B,
              const float* __restrict__ freqs, int ybase) {
    extern __shared__ __align__(128) char dsm[];
    GemmCtx cx;
    gemm_mainloop(A, B, cx, dsm, ybase);

#pragma unroll
    for (int am = 0; am < 4; am++) {
        int row0 = cx.bm + (cx.wid >> 2) * 64 + am * 16 + (cx.L >> 2);
#pragma unroll
        for (int half = 0; half < 2; half++) {
            const int row = row0 + half * 8;
            const int l = row & (SEQ - 1);
            const int b = row >> 11;
#pragma unroll
            for (int g = 0; g < 4; g++) {
                int col = cx.bn + (cx.wid & 3) * 32 + g * 8 + (cx.L & 3) * 2;
                float v0 = cx.acc[am][g][2 * half];
                float v1 = cx.acc[am][g][2 * half + 1];
                if (col < 2048) {                         // q: rope + 0.125
                    int h = col >> 6, d = col & 63, p = d >> 1;
                    float c = freqs[l * 32 + p];
                    float s = freqs[SEQ * 32 + l * 32 + p];
                    float r0 = (v0 * c - v1 * s) * 0.125f;
                    float r1 = (v0 * s + v1 * c) * 0.125f;
                    *(uint32_t*)(g_qs + ((size_t)(b * NH + h) * SEQ + l) * 64 + d) = f2h2(r0, r1);
                } else if (col < 2560) {                  // k: rope
                    int kh = (col - 2048) >> 6, d = (col - 2048) & 63, p = d >> 1;
                    float c = freqs[l * 32 + p];
                    float s = freqs[SEQ * 32 + l * 32 + p];
                    float r0 = v0 * c - v1 * s;
                    float r1 = v0 * s + v1 * c;
                    *(uint32_t*)(g_ks + ((size_t)(b * NKV + kh) * SEQ + l) * 64 + d) = f2h2(r0, r1);
                } else {                                  // v: plain
                    int kh = (col - 2560) >> 6, d = (col - 2560) & 63;
                    *(uint32_t*)(g_vs + ((size_t)(b * NKV + kh) * SEQ + l) * 64 + d) = f2h2(v0, v1);
                }
            }
        }
    }
}

// ---------------------------------------------------------------------------
// Single-pass fp16 causal flash attention for ONE batch (param b).
// grid (SEQ/128, NH); 256 threads. LPT: heavy tiles first.
// ---------------------------------------------------------------------------
constexpr int FA_STR = 144;
constexpr int FA_Q   = 0;
constexpr int FA_KV  = 128 * FA_STR;
constexpr int FA_SMEM = FA_KV + 4 * 64 * FA_STR;   // 55296
constexpr float LOG2E = 1.4426950408889634f;

__global__ __launch_bounds__(256, 2)
void flash_attn_f16(const __half* __restrict__ Qs,
                    const __half* __restrict__ Ks,
                    const __half* __restrict__ Vs, int b) {
    extern __shared__ __align__(128) char fsm[];
    const uint32_t base = smem_u32(fsm);
    const uint32_t sQ = base + FA_Q;

    const int tid = threadIdx.x;
    const int wid = tid >> 5;
    const int L = tid & 31;
    const int wm = wid * 16;
    const uint32_t lrow = L & 15;
    const uint32_t lcol16 = (L >> 4) * 16;

    const int m0 = (gridDim.x - 1 - blockIdx.x) * 128;   // LPT: heavy first
    const int h = blockIdx.y;
    const int kvh = h >> 2;

    const __half* qsrc = Qs + ((size_t)(b * NH + h) * SEQ + m0) * 64;
#pragma unroll
    for (int u = 0; u < 4; u++) {
        int e = tid + u * 256;
        int row = e >> 3, ch = e & 7;
        cp_async16(sQ + row * FA_STR + ch * 16, qsrc + (size_t)row * 64 + ch * 8);
    }
    cp_commit();
    asm volatile("cp.async.wait_group 0;" ::: "memory");
    __syncthreads();

    uint32_t qf[4][4];
#pragma unroll
    for (int kg = 0; kg < 4; kg++)
        ldm_x4(qf[kg], sQ + (wm + lrow) * FA_STR + kg * 32 + lcol16);

    float O[8][4];
#pragma unroll
    for (int i = 0; i < 8; i++)
#pragma unroll
        for (int j = 0; j < 4; j++) O[i][j] = 0.f;
    float mr0 = -1e30f, mr1 = -1e30f, lr0 = 0.f, lr1 = 0.f;

    const __half* ksrc = Ks + (size_t)(b * NKV + kvh) * SEQ * 64;
    const __half* vsrc = Vs + (size_t)(b * NKV + kvh) * SEQ * 64;

    auto load_kv = [&](int t) {
        const int n0 = t * 64;
        const uint32_t kb = base + FA_KV + (t & 1) * 18432;
        const uint32_t vb = kb + 9216;
#pragma unroll
        for (int u = 0; u < 2; u++) {
            int e = tid + u * 256;
            int row = e >> 3, ch = e & 7;
            cp_async16(kb + row * FA_STR + ch * 16, ksrc + (size_t)(n0 + row) * 64 + ch * 8);
            cp_async16(vb + row * FA_STR + ch * 16, vsrc + (size_t)(n0 + row) * 64 + ch * 8);
        }
    };

    const int nT = m0 / 64 + 2;
    load_kv(0); cp_commit();

    for (int t = 0; t < nT; t++) {
        if (t + 1 < nT) load_kv(t + 1);
        cp_commit();
        asm volatile("cp.async.wait_group 1;" ::: "memory");
        __syncthreads();

        const int n0 = t * 64;
        const uint32_t kb = base + FA_KV + (t & 1) * 18432;
        const uint32_t vb = kb + 9216;
        const bool active = (n0 <= m0 + wm + 15);

        if (active) {
            float S[8][4];
#pragma unroll
            for (int i = 0; i < 8; i++)
#pragma unroll
                for (int j = 0; j < 4; j++) S[i][j] = 0.f;

#pragma unroll
            for (int kg = 0; kg < 4; kg++) {
                uint32_t kf[4][4];
#pragma unroll
                for (int nn = 0; nn < 4; nn++)
                    ldm_x4(kf[nn], kb + (nn * 16 + lrow) * FA_STR + kg * 32 + lcol16);
#pragma unroll
                for (int ng = 0; ng < 8; ng++)
                    mma_f16(S[ng], qf[kg], kf[ng >> 1][ng & 1], kf[ng >> 1][2 + (ng & 1)]);
            }

            const int r0 = m0 + wm + (L >> 2);
            const int r1 = r0 + 8;
            if (n0 + 63 > m0 + wm) {
#pragma unroll
                for (int ng = 0; ng < 8; ng++) {
                    int c0 = n0 + ng * 8 + (L & 3) * 2;
                    if (c0 > r0)     S[ng][0] = -1e30f;
                    if (c0 + 1 > r0) S[ng][1] = -1e30f;
                    if (c0 > r1)     S[ng][2] = -1e30f;
                    if (c0 + 1 > r1) S[ng][3] = -1e30f;
                }
            }

            float t0 = -1e30f, t1 = -1e30f;
#pragma unroll
            for (int ng = 0; ng < 8; ng++) {
                t0 = fmaxf(t0, fmaxf(S[ng][0], S[ng][1]));
                t1 = fmaxf(t1, fmaxf(S[ng][2], S[ng][3]));
            }
            t0 = fmaxf(t0, __shfl_xor_sync(0xffffffffu, t0, 1));
            t0 = fmaxf(t0, __shfl_xor_sync(0xffffffffu, t0, 2));
            t1 = fmaxf(t1, __shfl_xor_sync(0xffffffffu, t1, 1));
            t1 = fmaxf(t1, __shfl_xor_sync(0xffffffffu, t1, 2));

            float mn0 = fmaxf(mr0, t0), mn1 = fmaxf(mr1, t1);
            float corr0 = ex2f((mr0 - mn0) * LOG2E);
            float corr1 = ex2f((mr1 - mn1) * LOG2E);
            lr0 *= corr0; lr1 *= corr1;
#pragma unroll
            for (int ng = 0; ng < 8; ng++) {
                O[ng][0] *= corr0; O[ng][1] *= corr0;
                O[ng][2] *= corr1; O[ng][3] *= corr1;
            }
            mr0 = mn0; mr1 = mn1;
            const float mb0 = mn0 * LOG2E, mb1 = mn1 * LOG2E;

            uint32_t pa[4][4];
            float s0 = 0.f, s1 = 0.f;
#pragma unroll
            for (int kg = 0; kg < 4; kg++) {
                float p[8];
#pragma unroll
                for (int e = 0; e < 2; e++) {
                    const int g = 2 * kg + e;
                    p[4 * e + 0] = ex2f(fmaf(S[g][0], LOG2E, -mb0));
                    p[4 * e + 1] = ex2f(fmaf(S[g][1], LOG2E, -mb0));
                    p[4 * e + 2] = ex2f(fmaf(S[g][2], LOG2E, -mb1));
                    p[4 * e + 3] = ex2f(fmaf(S[g][3], LOG2E, -mb1));
                    s0 += p[4 * e] + p[4 * e + 1];
                    s1 += p[4 * e + 2] + p[4 * e + 3];
                }
                pa[kg][0] = f2h2(p[0], p[1]);
                pa[kg][1] = f2h2(p[2], p[3]);
                pa[kg][2] = f2h2(p[4], p[5]);
                pa[kg][3] = f2h2(p[6], p[7]);
            }
            s0 += __shfl_xor_sync(0xffffffffu, s0, 1);
            s0 += __shfl_xor_sync(0xffffffffu, s0, 2);
            s1 += __shfl_xor_sync(0xffffffffu, s1, 1);
            s1 += __shfl_xor_sync(0xffffffffu, s1, 2);
            lr0 += s0; lr1 += s1;

#pragma unroll
            for (int kg = 0; kg < 4; kg++) {
                uint32_t vf[4][4];
#pragma unroll
                for (int cp = 0; cp < 4; cp++)
                    ldm_x4_t(vf[cp], vb + (kg * 16 + lrow) * FA_STR + cp * 32 + lcol16);
#pragma unroll
                for (int cp = 0; cp < 4; cp++) {
#pragma unroll
                    for (int e = 0; e < 2; e++) {
                        const int ng = 2 * cp + e;
                        mma_f16(O[ng], pa[kg], vf[cp][2 * e], vf[cp][2 * e + 1]);
                    }
                }
            }
        }
        __syncthreads();
    }

    const float inv0 = 1.f / lr0;
    const float inv1 = 1.f / lr1;
    const int mb = (b * SEQ + m0 + wm) >> 4;
#pragma unroll
    for (int ng = 0; ng < 8; ng++) {
        const int kc16 = h * 4 + (ng >> 1);
        uint32_t* w = g_at + ((size_t)(mb * 128 + kc16) * 32 + L) * 4 + (ng & 1) * 2;
        w[0] = f2h2(O[ng][0] * inv0, O[ng][1] * inv0);
        w[1] = f2h2(O[ng][2] * inv1, O[ng][3] * inv1);
    }
}

// ---------------------------------------------------------------------------
extern "C" void kernel_launch(void* const* d_in, const int* in_sizes, int n_in,
                              void* d_out, int out_size) {
    const float* x     = (const float*)d_in[0];
    const float* freqs = (const float*)d_in[1];
    const float* wq    = (const float*)d_in[2];
    const float* wk    = (const float*)d_in[3];
    const float* wv    = (const float*)d_in[4];
    const float* wo    = (const float*)d_in[5];
    float* out = (float*)d_out;

    uint32_t *xt, *wqkvt, *wot, *at;
    __half *qs, *ks, *vs;
    cudaGetSymbolAddress((void**)&xt, g_xt);
    cudaGetSymbolAddress((void**)&wqkvt, g_wqkvt);
    cudaGetSymbolAddress((void**)&wot, g_wot);
    cudaGetSymbolAddress((void**)&at, g_at);
    cudaGetSymbolAddress((void**)&qs, g_qs);
    cudaGetSymbolAddress((void**)&ks, g_ks);
    cudaGetSymbolAddress((void**)&vs, g_vs);

    static bool init_done = false;
    static cudaStream_t s1 = 0;
    static cudaEvent_t ev0, evA, evB, evC, evD;
    if (!init_done) {
        cudaFuncSetAttribute(gemm_f16, cudaFuncAttributeMaxDynamicSharedMemorySize, GSMEM);
        cudaFuncSetAttribute(gemm_qkv, cudaFuncAttributeMaxDynamicSharedMemorySize, GSMEM);
        cudaFuncSetAttribute(flash_attn_f16, cudaFuncAttributeMaxDynamicSharedMemorySize, FA_SMEM);
        if (cudaStreamCreateWithFlags(&s1, cudaStreamNonBlocking) != cudaSuccess) s1 = 0;
        cudaEventCreateWithFlags(&ev0, cudaEventDisableTiming);
        cudaEventCreateWithFlags(&evA, cudaEventDisableTiming);
        cudaEventCreateWithFlags(&evB, cudaEventDisableTiming);
        cudaEventCreateWithFlags(&evC, cudaEventDisableTiming);
        cudaEventCreateWithFlags(&evD, cudaEventDisableTiming);
        init_done = true;
    }
    cudaStream_t s0 = 0;

    // fork side stream into the capture DAG
    cudaEventRecord(ev0, s0);
    cudaStreamWaitEvent(s1, ev0, 0);

    // packs: main on s0, wo on s1 (parallel)
    pack_main<<<7168, 256, 0, s0>>>(x, wq, wk, wv);
    pack_wo<<<2048, 256, 0, s1>>>(wo);

    // QKV projection, batch 0 rows
    gemm_qkv<<<dim3(NQKV / 128, 16), 256, GSMEM, s0>>>(xt, wqkvt, freqs, 0);
    cudaEventRecord(evA, s0);

    // attention b=0 on s1 (after QKV b0); QKV batch 1 on s0 concurrently
    cudaStreamWaitEvent(s1, evA, 0);
    flash_attn_f16<<<dim3(SEQ / 128, NH), 256, FA_SMEM, s1>>>(qs, ks, vs, 0);
    cudaEventRecord(evB, s1);

    gemm_qkv<<<dim3(NQKV / 128, 16), 256, GSMEM, s0>>>(xt, wqkvt, freqs, 16);
    cudaEventRecord(evC, s0);

    // attention b=1 on s1; O-proj b0 on s0 concurrently
    cudaStreamWaitEvent(s1, evC, 0);
    flash_attn_f16<<<dim3(SEQ / 128, NH), 256, FA_SMEM, s1>>>(qs, ks, vs, 1);
    cudaEventRecord(evD, s1);

    cudaStreamWaitEvent(s0, evB, 0);
    gemm_f16<<<dim3(DIMM / 128, 16), 256, GSMEM, s0>>>(at, wot, out, DIMM, 0);

    cudaStreamWaitEvent(s0, evD, 0);
    gemm_f16<<<dim3(DIMM / 128, 16), 256, GSMEM, s0>>>(at, wot, out, DIMM, 16);
}

// round 16
// speedup vs baseline: 1.0569x; 1.0569x over previous
#include <cuda_runtime.h>
#include <cuda_fp16.h>
#include <cstdint>
#include <cstddef>

// Problem constants
constexpr int BB   = 2;
constexpr int SEQ  = 2048;
constexpr int DIMM = 2048;
constexpr int NH   = 32;
constexpr int NKV  = 8;
constexpr int HDIM = 64;
constexpr int MROWS = BB * SEQ;                    // 4096
constexpr int NQKV  = NH * HDIM + 2 * NKV * HDIM;  // 3072

// ---------------------------------------------------------------------------
// Scratch (device globals; allocation-free rule)
// Fragment-packed fp16 operands (m16n8k16):
//  A-pack: [mb=row/16][kc16=k/16 (128)][lane][4 half2 words]
//  B-pack: [nb=n/8][kc32=k/32 (64)][lane][4 half2 words]
// ---------------------------------------------------------------------------
__device__ uint32_t g_xt[MROWS * DIMM / 2];         // packed x           16 MB
__device__ uint32_t g_wqkvt[NQKV * DIMM / 2];       // packed wq|wk|wv    12 MB
__device__ uint32_t g_wot[DIMM * DIMM / 2];         // packed wo           8 MB
__device__ uint32_t g_at[MROWS * DIMM / 2];         // packed attn out    16 MB
// attention inputs, fp16, 64 per row
__device__ __half g_qs[BB * NH * SEQ * HDIM];       // 16 MB (q roped, /8)
__device__ __half g_ks[BB * NKV * SEQ * HDIM];      // 4 MB  (k roped)
__device__ __half g_vs[BB * NKV * SEQ * HDIM];      // 4 MB

// ---------------------------------------------------------------------------
// Helpers
// ---------------------------------------------------------------------------
__device__ __forceinline__ uint32_t smem_u32(const void* p) {
    uint32_t a;
    asm("{ .reg .u64 t; cvta.to.shared.u64 t, %1; cvt.u32.u64 %0, t; }" : "=r"(a) : "l"(p));
    return a;
}
__device__ __forceinline__ void cp_async16(uint32_t dst, const void* src) {
    asm volatile("cp.async.cg.shared.global [%0], [%1], 16;" :: "r"(dst), "l"(src));
}
__device__ __forceinline__ void cp_commit() { asm volatile("cp.async.commit_group;" ::: "memory"); }

__device__ __forceinline__ void lds128(uint32_t* r, uint32_t addr) {
    asm volatile("ld.shared.v4.b32 {%0,%1,%2,%3}, [%4];"
        : "=r"(r[0]), "=r"(r[1]), "=r"(r[2]), "=r"(r[3]) : "r"(addr));
}
__device__ __forceinline__ void ldm_x4(uint32_t* r, uint32_t addr) {
    asm volatile("ldmatrix.sync.aligned.m8n8.x4.shared.b16 {%0,%1,%2,%3}, [%4];"
        : "=r"(r[0]), "=r"(r[1]), "=r"(r[2]), "=r"(r[3]) : "r"(addr));
}
__device__ __forceinline__ void ldm_x4_t(uint32_t* r, uint32_t addr) {
    asm volatile("ldmatrix.sync.aligned.m8n8.x4.trans.shared.b16 {%0,%1,%2,%3}, [%4];"
        : "=r"(r[0]), "=r"(r[1]), "=r"(r[2]), "=r"(r[3]) : "r"(addr));
}
__device__ __forceinline__ void mma_f16(float* d, const uint32_t* a, uint32_t b0, uint32_t b1) {
    asm volatile("mma.sync.aligned.m16n8k16.row.col.f32.f16.f16.f32 "
        "{%0,%1,%2,%3}, {%4,%5,%6,%7}, {%8,%9}, {%0,%1,%2,%3};"
        : "+f"(d[0]), "+f"(d[1]), "+f"(d[2]), "+f"(d[3])
        : "r"(a[0]), "r"(a[1]), "r"(a[2]), "r"(a[3]), "r"(b0), "r"(b1));
}
__device__ __forceinline__ uint32_t f2h2(float lo, float hi) {
    __half2 h = __floats2half2_rn(lo, hi);
    return *(uint32_t*)&h;
}
__device__ __forceinline__ float ex2f(float x) {
    float r;
    asm("ex2.approx.f32 %0, %1;" : "=f"(r) : "f"(x));
    return r;
}

// ---------------------------------------------------------------------------
// pack_a: fp32 [rows][2048] -> fp16 A-fragment pack (m16n8k16).
// ---------------------------------------------------------------------------
__global__ __launch_bounds__(256) void pack_a(const float* __restrict__ src,
                                              uint32_t* __restrict__ dst,
                                              int mb0, int nmb) {
    int idx = blockIdx.x * 256 + threadIdx.x;
    if (idx >= nmb * 4096) return;
    int lane = idx & 31;
    int kc16 = (idx >> 5) & 127;
    int mb = (idx >> 12) + mb0;
    int r = lane >> 2;
    int c2 = kc16 * 16 + (lane & 3) * 2;
    const float* s = src + (size_t)mb * 16 * 2048;
    uint4 o;
    o.x = f2h2(s[(size_t)r * 2048 + c2],        s[(size_t)r * 2048 + c2 + 1]);
    o.y = f2h2(s[(size_t)(r + 8) * 2048 + c2],  s[(size_t)(r + 8) * 2048 + c2 + 1]);
    o.z = f2h2(s[(size_t)r * 2048 + c2 + 8],    s[(size_t)r * 2048 + c2 + 9]);
    o.w = f2h2(s[(size_t)(r + 8) * 2048 + c2 + 8], s[(size_t)(r + 8) * 2048 + c2 + 9]);
    ((uint4*)dst)[(size_t)mb * 4096 + (idx & 4095)] = o;
}

// ---------------------------------------------------------------------------
// pack_b: weights [N][2048] -> fp16 B-fragment pack.
// ---------------------------------------------------------------------------
__global__ __launch_bounds__(256) void pack_b(const float* __restrict__ src,
                                              uint32_t* __restrict__ dst, int total) {
    int idx = blockIdx.x * 256 + threadIdx.x;
    if (idx >= total) return;
    int lane = idx & 31;
    int kc32 = (idx >> 5) & 63;
    int nb = idx >> 11;
    int n = nb * 8 + (lane >> 2);
    int k2 = kc32 * 32 + (lane & 3) * 2;
    const float* s = src + (size_t)n * 2048 + k2;
    uint4 o;
    o.x = f2h2(s[0],  s[1]);
    o.y = f2h2(s[8],  s[9]);
    o.z = f2h2(s[16], s[17]);
    o.w = f2h2(s[24], s[25]);
    ((uint4*)dst)[idx] = o;
}

__global__ __launch_bounds__(256) void pack_b_qkv(const float* __restrict__ wq,
                                                  const float* __restrict__ wk,
                                                  const float* __restrict__ wv,
                                                  uint32_t* __restrict__ dst, int total) {
    int idx = blockIdx.x * 256 + threadIdx.x;
    if (idx >= total) return;
    int lane = idx & 31;
    int kc32 = (idx >> 5) & 63;
    int nb = idx >> 11;
    int n = nb * 8 + (lane >> 2);
    int k2 = kc32 * 32 + (lane & 3) * 2;
    const float* s;
    if (n < 2048)      s = wq + (size_t)n * 2048 + k2;
    else if (n < 2560) s = wk + (size_t)(n - 2048) * 2048 + k2;
    else               s = wv + (size_t)(n - 2560) * 2048 + k2;
    uint4 o;
    o.x = f2h2(s[0],  s[1]);
    o.y = f2h2(s[8],  s[9]);
    o.z = f2h2(s[16], s[17]);
    o.w = f2h2(s[24], s[25]);
    ((uint4*)dst)[idx] = o;
}

// ---------------------------------------------------------------------------
// GEMM mainloop: CTA 128x128, 128 threads = 4 warps (2x2), warp tile 64x64,
// K-chunk 32 (64 iterations), 3-stage cp.async pipeline (16KB/stage),
// 2 CTAs/SM.
// ---------------------------------------------------------------------------
constexpr int FSTAGE = 16384;
constexpr int GSMEM  = 3 * FSTAGE;                 // 49152

struct GemmCtx {
    float acc[4][8][4];
    int bm, bn, wid, L;
};

__device__ __forceinline__ void gemm_mainloop(const uint32_t* __restrict__ A,
                                              const uint32_t* __restrict__ B,
                                              GemmCtx& cx, char* dsm) {
    const int tid = threadIdx.x;
    const int wid = tid >> 5;
    const int L = tid & 31;
    const uint32_t base = smem_u32(dsm);
    cx.bm = blockIdx.y * 128;
    cx.bn = blockIdx.x * 128;
    cx.wid = wid; cx.L = L;
    const uint32_t* Ab = A + (size_t)(cx.bm >> 4) * 16384;
    const uint32_t* Bb = B + (size_t)(cx.bn >> 3) * 8192;

#pragma unroll
    for (int i = 0; i < 4; i++)
#pragma unroll
        for (int j = 0; j < 8; j++)
#pragma unroll
            for (int q = 0; q < 4; q++) cx.acc[i][j][q] = 0.f;

    auto load_stage = [&](int s, int c) {
        const uint32_t sb = base + s * FSTAGE;
#pragma unroll
        for (int u = 0; u < 4; u++) {            // A: 512 uint4
            int e = tid + u * 128;
            int lane = e & 31, kcl = (e >> 5) & 1, mb = e >> 6;
            cp_async16(sb + e * 16,
                       Ab + (((size_t)mb * 128 + c * 2 + kcl) * 32 + lane) * 4);
        }
#pragma unroll
        for (int u = 0; u < 4; u++) {            // B: 512 uint4
            int e = tid + u * 128;
            int lane = e & 31, nb = e >> 5;
            cp_async16(sb + 8192 + e * 16,
                       Bb + (((size_t)nb * 64 + c) * 32 + lane) * 4);
        }
    };

    load_stage(0, 0); cp_commit();
    load_stage(1, 1); cp_commit();

    const int wmb = (wid >> 1) * 4;     // warp A mb base (m/16)
    const int wnb = (wid & 1) * 8;      // warp B nb base (n/8)

    for (int i = 0; i < 64; i++) {
        asm volatile("cp.async.wait_group 1;" ::: "memory");
        __syncthreads();
        if (i + 2 < 64) load_stage((i + 2) % 3, i + 2);
        cp_commit();

        const uint32_t sA = base + (i % 3) * FSTAGE;
        const uint32_t sB = sA + 8192;
        uint32_t b[8][4];
#pragma unroll
        for (int g = 0; g < 8; g++)
            lds128(b[g], sB + ((wnb + g) * 32 + L) * 16);
#pragma unroll
        for (int kcl = 0; kcl < 2; kcl++) {
            uint32_t a[4][4];
#pragma unroll
            for (int am = 0; am < 4; am++)
                lds128(a[am], sA + (((wmb + am) * 2 + kcl) * 32 + L) * 16);
#pragma unroll
            for (int am = 0; am < 4; am++)
#pragma unroll
                for (int g = 0; g < 8; g++)
                    mma_f16(cx.acc[am][g], a[am], b[g][2 * kcl], b[g][2 * kcl + 1]);
        }
    }
}

// ---------------------------------------------------------------------------
// O-projection GEMM: plain fp32 epilogue to d_out.
// ---------------------------------------------------------------------------
__global__ __launch_bounds__(128, 2)
void gemm_f16(const uint32_t* __restrict__ A, const uint32_t* __restrict__ B,
              float* __restrict__ C, int Ntot) {
    extern __shared__ __align__(128) char dsm[];
    GemmCtx cx;
    gemm_mainloop(A, B, cx, dsm);
#pragma unroll
    for (int am = 0; am < 4; am++) {
        int row = cx.bm + (cx.wid >> 1) * 64 + am * 16 + (cx.L >> 2);
#pragma unroll
        for (int g = 0; g < 8; g++) {
            int col = cx.bn + (cx.wid & 1) * 64 + g * 8 + (cx.L & 3) * 2;
            *(float2*)(C + (size_t)row * Ntot + col) = make_float2(cx.acc[am][g][0], cx.acc[am][g][1]);
            *(float2*)(C + (size_t)(row + 8) * Ntot + col) = make_float2(cx.acc[am][g][2], cx.acc[am][g][3]);
        }
    }
}

// ---------------------------------------------------------------------------
// QKV GEMM with fused RoPE + fp16 epilogue writing g_qs/g_ks/g_vs.
// ---------------------------------------------------------------------------
__global__ __launch_bounds__(128, 2)
void gemm_qkv(const uint32_t* __restrict__ A, const uint32_t* __restrict__ B,
              const float* __restrict__ freqs) {
    extern __shared__ __align__(128) char dsm[];
    GemmCtx cx;
    gemm_mainloop(A, B, cx, dsm);

#pragma unroll
    for (int am = 0; am < 4; am++) {
        int row0 = cx.bm + (cx.wid >> 1) * 64 + am * 16 + (cx.L >> 2);
#pragma unroll
        for (int half = 0; half < 2; half++) {
            const int row = row0 + half * 8;
            const int l = row & (SEQ - 1);
            const int b = row >> 11;
#pragma unroll
            for (int g = 0; g < 8; g++) {
                int col = cx.bn + (cx.wid & 1) * 64 + g * 8 + (cx.L & 3) * 2;
                float v0 = cx.acc[am][g][2 * half];
                float v1 = cx.acc[am][g][2 * half + 1];
                if (col < 2048) {                         // q: rope + 0.125
                    int h = col >> 6, d = col & 63, p = d >> 1;
                    float c = freqs[l * 32 + p];
                    float s = freqs[SEQ * 32 + l * 32 + p];
                    float r0 = (v0 * c - v1 * s) * 0.125f;
                    float r1 = (v0 * s + v1 * c) * 0.125f;
                    *(uint32_t*)(g_qs + ((size_t)(b * NH + h) * SEQ + l) * 64 + d) = f2h2(r0, r1);
                } else if (col < 2560) {                  // k: rope
                    int kh = (col - 2048) >> 6, d = (col - 2048) & 63, p = d >> 1;
                    float c = freqs[l * 32 + p];
                    float s = freqs[SEQ * 32 + l * 32 + p];
                    float r0 = v0 * c - v1 * s;
                    float r1 = v0 * s + v1 * c;
                    *(uint32_t*)(g_ks + ((size_t)(b * NKV + kh) * SEQ + l) * 64 + d) = f2h2(r0, r1);
                } else {                                  // v: plain
                    int kh = (col - 2560) >> 6, d = (col - 2560) & 63;
                    *(uint32_t*)(g_vs + ((size_t)(b * NKV + kh) * SEQ + l) * 64 + d) = f2h2(v0, v1);
                }
            }
        }
    }
}

// ---------------------------------------------------------------------------
// Single-pass fp16 causal flash attention; epilogue writes g_at in
// A-fragment-packed layout (feeds O projection directly).
// grid (SEQ/128, NH, BB); 256 threads = 8 warps x 16 query rows.
// ---------------------------------------------------------------------------
constexpr int FA_STR = 144;
constexpr int FA_Q   = 0;                          // 18432 B
constexpr int FA_KV  = 128 * FA_STR;
constexpr int FA_SMEM = FA_KV + 4 * 64 * FA_STR;   // 55296
constexpr float LOG2E = 1.4426950408889634f;

__global__ __launch_bounds__(256, 2)
void flash_attn_f16(const __half* __restrict__ Qs,
                    const __half* __restrict__ Ks,
                    const __half* __restrict__ Vs) {
    extern __shared__ __align__(128) char fsm[];
    const uint32_t base = smem_u32(fsm);
    const uint32_t sQ = base + FA_Q;

    const int tid = threadIdx.x;
    const int wid = tid >> 5;
    const int L = tid & 31;
    const int wm = wid * 16;
    const uint32_t lrow = L & 15;
    const uint32_t lcol16 = (L >> 4) * 16;

    const int m0 = blockIdx.x * 128;
    const int h = blockIdx.y;
    const int b = blockIdx.z;
    const int kvh = h >> 2;

    const __half* qsrc = Qs + ((size_t)(b * NH + h) * SEQ + m0) * 64;
#pragma unroll
    for (int u = 0; u < 4; u++) {
        int e = tid + u * 256;
        int row = e >> 3, ch = e & 7;
        cp_async16(sQ + row * FA_STR + ch * 16, qsrc + (size_t)row * 64 + ch * 8);
    }
    cp_commit();
    asm volatile("cp.async.wait_group 0;" ::: "memory");
    __syncthreads();

    uint32_t qf[4][4];
#pragma unroll
    for (int kg = 0; kg < 4; kg++)
        ldm_x4(qf[kg], sQ + (wm + lrow) * FA_STR + kg * 32 + lcol16);

    float O[8][4];
#pragma unroll
    for (int i = 0; i < 8; i++)
#pragma unroll
        for (int j = 0; j < 4; j++) O[i][j] = 0.f;
    float mr0 = -1e30f, mr1 = -1e30f, lr0 = 0.f, lr1 = 0.f;

    const __half* ksrc = Ks + (size_t)(b * NKV + kvh) * SEQ * 64;
    const __half* vsrc = Vs + (size_t)(b * NKV + kvh) * SEQ * 64;

    auto load_kv = [&](int t) {
        const int n0 = t * 64;
        const uint32_t kb = base + FA_KV + (t & 1) * 18432;
        const uint32_t vb = kb + 9216;
#pragma unroll
        for (int u = 0; u < 2; u++) {
            int e = tid + u * 256;
            int row = e >> 3, ch = e & 7;
            cp_async16(kb + row * FA_STR + ch * 16, ksrc + (size_t)(n0 + row) * 64 + ch * 8);
            cp_async16(vb + row * FA_STR + ch * 16, vsrc + (size_t)(n0 + row) * 64 + ch * 8);
        }
    };

    const int nT = m0 / 64 + 2;
    load_kv(0); cp_commit();

    for (int t = 0; t < nT; t++) {
        if (t + 1 < nT) load_kv(t + 1);
        cp_commit();
        asm volatile("cp.async.wait_group 1;" ::: "memory");
        __syncthreads();

        const int n0 = t * 64;
        const uint32_t kb = base + FA_KV + (t & 1) * 18432;
        const uint32_t vb = kb + 9216;
        const bool active = (n0 <= m0 + wm + 15);

        if (active) {
            float S[8][4];
#pragma unroll
            for (int i = 0; i < 8; i++)
#pragma unroll
                for (int j = 0; j < 4; j++) S[i][j] = 0.f;

#pragma unroll
            for (int kg = 0; kg < 4; kg++) {
                uint32_t kf[4][4];
#pragma unroll
                for (int nn = 0; nn < 4; nn++)
                    ldm_x4(kf[nn], kb + (nn * 16 + lrow) * FA_STR + kg * 32 + lcol16);
#pragma unroll
                for (int ng = 0; ng < 8; ng++)
                    mma_f16(S[ng], qf[kg], kf[ng >> 1][ng & 1], kf[ng >> 1][2 + (ng & 1)]);
            }

            const int r0 = m0 + wm + (L >> 2);
            const int r1 = r0 + 8;
            if (n0 + 63 > m0 + wm) {
#pragma unroll
                for (int ng = 0; ng < 8; ng++) {
                    int c0 = n0 + ng * 8 + (L & 3) * 2;
                    if (c0 > r0)     S[ng][0] = -1e30f;
                    if (c0 + 1 > r0) S[ng][1] = -1e30f;
                    if (c0 > r1)     S[ng][2] = -1e30f;
                    if (c0 + 1 > r1) S[ng][3] = -1e30f;
                }
            }

            float t0 = -1e30f, t1 = -1e30f;
#pragma unroll
            for (int ng = 0; ng < 8; ng++) {
                t0 = fmaxf(t0, fmaxf(S[ng][0], S[ng][1]));
                t1 = fmaxf(t1, fmaxf(S[ng][2], S[ng][3]));
            }
            t0 = fmaxf(t0, __shfl_xor_sync(0xffffffffu, t0, 1));
            t0 = fmaxf(t0, __shfl_xor_sync(0xffffffffu, t0, 2));
            t1 = fmaxf(t1, __shfl_xor_sync(0xffffffffu, t1, 1));
            t1 = fmaxf(t1, __shfl_xor_sync(0xffffffffu, t1, 2));

            float mn0 = fmaxf(mr0, t0), mn1 = fmaxf(mr1, t1);
            float corr0 = ex2f((mr0 - mn0) * LOG2E);
            float corr1 = ex2f((mr1 - mn1) * LOG2E);
            lr0 *= corr0; lr1 *= corr1;
#pragma unroll
            for (int ng = 0; ng < 8; ng++) {
                O[ng][0] *= corr0; O[ng][1] *= corr0;
                O[ng][2] *= corr1; O[ng][3] *= corr1;
            }
            mr0 = mn0; mr1 = mn1;
            const float mb0 = mn0 * LOG2E, mb1 = mn1 * LOG2E;

            uint32_t pa[4][4];
            float s0 = 0.f, s1 = 0.f;
#pragma unroll
            for (int kg = 0; kg < 4; kg++) {
                float p[8];
#pragma unroll
                for (int e = 0; e < 2; e++) {
                    const int g = 2 * kg + e;
                    p[4 * e + 0] = ex2f(fmaf(S[g][0], LOG2E, -mb0));
                    p[4 * e + 1] = ex2f(fmaf(S[g][1], LOG2E, -mb0));
                    p[4 * e + 2] = ex2f(fmaf(S[g][2], LOG2E, -mb1));
                    p[4 * e + 3] = ex2f(fmaf(S[g][3], LOG2E, -mb1));
                    s0 += p[4 * e] + p[4 * e + 1];
                    s1 += p[4 * e + 2] + p[4 * e + 3];
                }
                pa[kg][0] = f2h2(p[0], p[1]);
                pa[kg][1] = f2h2(p[2], p[3]);
                pa[kg][2] = f2h2(p[4], p[5]);
                pa[kg][3] = f2h2(p[6], p[7]);
            }
            s0 += __shfl_xor_sync(0xffffffffu, s0, 1);
            s0 += __shfl_xor_sync(0xffffffffu, s0, 2);
            s1 += __shfl_xor_sync(0xffffffffu, s1, 1);
            s1 += __shfl_xor_sync(0xffffffffu, s1, 2);
            lr0 += s0; lr1 += s1;

#pragma unroll
            for (int kg = 0; kg < 4; kg++) {
                uint32_t vf[4][4];
#pragma unroll
                for (int cp = 0; cp < 4; cp++)
                    ldm_x4_t(vf[cp], vb + (kg * 16 + lrow) * FA_STR + cp * 32 + lcol16);
#pragma unroll
                for (int cp = 0; cp < 4; cp++) {
#pragma unroll
                    for (int e = 0; e < 2; e++) {
                        const int ng = 2 * cp + e;
                        mma_f16(O[ng], pa[kg], vf[cp][2 * e], vf[cp][2 * e + 1]);
                    }
                }
            }
        }
        __syncthreads();
    }

    // ---- epilogue: write A-fragment-packed fp16 into g_at ----
    const float inv0 = 1.f / lr0;
    const float inv1 = 1.f / lr1;
    const int mb = (b * SEQ + m0 + wm) >> 4;
#pragma unroll
    for (int ng = 0; ng < 8; ng++) {
        const int kc16 = h * 4 + (ng >> 1);
        uint32_t* w = g_at + ((size_t)(mb * 128 + kc16) * 32 + L) * 4 + (ng & 1) * 2;
        w[0] = f2h2(O[ng][0] * inv0, O[ng][1] * inv0);
        w[1] = f2h2(O[ng][2] * inv1, O[ng][3] * inv1);
    }
}

// ---------------------------------------------------------------------------
extern "C" void kernel_launch(void* const* d_in, const int* in_sizes, int n_in,
                              void* d_out, int out_size) {
    const float* x     = (const float*)d_in[0];
    const float* freqs = (const float*)d_in[1];
    const float* wq    = (const float*)d_in[2];
    const float* wk    = (const float*)d_in[3];
    const float* wv    = (const float*)d_in[4];
    const float* wo    = (const float*)d_in[5];
    float* out = (float*)d_out;

    uint32_t *xt, *wqkvt, *wot, *at;
    __half *qs, *ks, *vs;
    cudaGetSymbolAddress((void**)&xt, g_xt);
    cudaGetSymbolAddress((void**)&wqkvt, g_wqkvt);
    cudaGetSymbolAddress((void**)&wot, g_wot);
    cudaGetSymbolAddress((void**)&at, g_at);
    cudaGetSymbolAddress((void**)&qs, g_qs);
    cudaGetSymbolAddress((void**)&ks, g_ks);
    cudaGetSymbolAddress((void**)&vs, g_vs);

    static bool attr_done = false;
    if (!attr_done) {
        cudaFuncSetAttribute(gemm_f16, cudaFuncAttributeMaxDynamicSharedMemorySize, GSMEM);
        cudaFuncSetAttribute(gemm_qkv, cudaFuncAttributeMaxDynamicSharedMemorySize, GSMEM);
        cudaFuncSetAttribute(flash_attn_f16, cudaFuncAttributeMaxDynamicSharedMemorySize, FA_SMEM);
        attr_done = true;
    }

    // 1) pack x, 2) pack merged qkv weights, 3) pack wo
    pack_a<<<4096, 256>>>(x, xt, 0, 256);
    pack_b_qkv<<<(NQKV * 256) / 256, 256>>>(wq, wk, wv, wqkvt, NQKV * 256);
    pack_b<<<(DIMM * 256) / 256, 256>>>(wo, wot, DIMM * 256);

    // 4) fused QKV projection + RoPE + fp16 -> g_qs/g_ks/g_vs
    gemm_qkv<<<dim3(NQKV / 128, MROWS / 128), 128, GSMEM>>>(xt, wqkvt, freqs);

    // 5) fp16 attention -> fragment-packed g_at
    flash_attn_f16<<<dim3(SEQ / 128, NH, BB), 256, FA_SMEM>>>(qs, ks, vs);

    // 6) O projection -> d_out
    gemm_f16<<<dim3(DIMM / 128, MROWS / 128), 128, GSMEM>>>(at, wot, out, DIMM);
}